// round 10
// baseline (speedup 1.0000x reference)
#include <cuda_runtime.h>
#include <cuda_bf16.h>
#include <cstdint>

#define W 512
#define H 512
#define IMGS 128                       // 16 * 8
#define STRIP 32                       // output rows per warp-task
#define STRIPS (H / STRIP)             // 16
#define SEGS 2                         // column segments per row
#define SEGW 256                       // cols per warp segment
#define CPT 8                          // cols per thread
#define TASKS (IMGS * STRIPS * SEGS)   // 4096 warp-tasks
#define BLOCK 256
#define WPB (BLOCK / 32)               // 8
#define GRID (TASKS / WPB)             // 512
#define NELEM 33554432.0f
#define FULLM 0xffffffffu

#define RING 5                         // smem slots per warp
#define DEPTH 3                        // rows in flight ahead of consumption
#define SLOT 1056                      // bytes per slot (1040 data, 16B-mult)
#define CPYB 1040u                     // bulk copy size: 260 floats

__device__ float g_partials[GRID];
__device__ unsigned int g_count;       // zero-init; last block resets

__device__ __forceinline__ void mbar_init(unsigned int bar, unsigned int cnt) {
    asm volatile("mbarrier.init.shared.b64 [%0], %1;" :: "r"(bar), "r"(cnt) : "memory");
}
__device__ __forceinline__ void mbar_wait(unsigned int bar, unsigned int parity) {
    asm volatile(
        "{\n\t.reg .pred P;\n\t"
        "WL_%=:\n\t"
        "mbarrier.try_wait.parity.acquire.cta.shared::cta.b64 P, [%0], %1, 0x989680;\n\t"
        "@P bra.uni WD_%=;\n\t"
        "bra.uni WL_%=;\n\t"
        "WD_%=:\n\t}"
        :: "r"(bar), "r"(parity) : "memory");
}
__device__ __forceinline__ void bulk_fetch(unsigned int slot, const float* src,
                                           unsigned int bar) {
    asm volatile("mbarrier.arrive.expect_tx.shared.b64 _, [%0], %1;"
                 :: "r"(bar), "r"(CPYB) : "memory");
    asm volatile("cp.async.bulk.shared::cta.global.mbarrier::complete_tx::bytes "
                 "[%0], [%1], %2, [%3];"
                 :: "r"(slot), "l"(src), "r"(CPYB), "r"(bar) : "memory");
}

struct Carry {
    float xp[CPT];    // x[r-1]
    float erp[CPT];   // er[r-1]
    float xLp, xRp;   // halo x (lane0/lane31)
    float erpR;       // er[r-1][c1+1] (lane31)
};

// Compute on row r's data (xc), emit loss for row r-1, advance carry.
__device__ __forceinline__ void step_compute(const float xc[CPT], float xLc, float xRc,
                                             int lane, bool rightEdge,
                                             Carry& C, float& acc) {
    float vm[CPT];
#pragma unroll
    for (int i = 0; i < CPT; i++) vm[i] = fminf(C.xp[i], xc[i]);  // vertical erosion
    float vmL = fminf(C.xLp, xLc);
    float vmR = fminf(C.xRp, xRc);

    float left = __shfl_up_sync(FULLM, vm[CPT-1], 1);
    if (lane == 0) left = vmL;                       // symmetric pad via column clamp
    float ern[CPT];
    ern[0] = fminf(left, vm[0]);
#pragma unroll
    for (int i = 1; i < CPT; i++) ern[i] = fminf(vm[i-1], vm[i]);
    float ernR = fminf(vm[CPT-1], vmR);

    float h[CPT];
#pragma unroll
    for (int i = 0; i < CPT; i++) h[i] = fmaxf(C.erp[i], ern[i]);
    float hR = fmaxf(C.erpR, ernR);

    float hn = __shfl_down_sync(FULLM, h[0], 1);
    if (lane == 31) hn = rightEdge ? h[CPT-1] : hR;  // er[512]=er[511] at image edge
#pragma unroll
    for (int i = 0; i < CPT-1; i++) {
        float di = fmaxf(h[i], h[i+1]);
        float d = C.xp[i] - di;
        acc = fmaf(d, d, acc);
    }
    {
        float di = fmaxf(h[CPT-1], hn);
        float d = C.xp[CPT-1] - di;
        acc = fmaf(d, d, acc);
    }

#pragma unroll
    for (int i = 0; i < CPT; i++) { C.xp[i] = xc[i]; C.erp[i] = ern[i]; }
    C.xLp = xLc; C.xRp = xRc; C.erpR = ernR;
}

__device__ __forceinline__ void final_emit(int lane, bool rightEdge, Carry& C, float& acc) {
    float hn = __shfl_down_sync(FULLM, C.erp[0], 1);
    if (lane == 31) hn = rightEdge ? C.erp[CPT-1] : C.erpR;
#pragma unroll
    for (int i = 0; i < CPT-1; i++) {
        float di = fmaxf(C.erp[i], C.erp[i+1]);
        float d = C.xp[i] - di;
        acc = fmaf(d, d, acc);
    }
    float di = fmaxf(C.erp[CPT-1], hn);
    float d = C.xp[CPT-1] - di;
    acc = fmaf(d, d, acc);
}

__global__ void __launch_bounds__(BLOCK, 4)
opening_loss_kernel(const float* __restrict__ labels, float* __restrict__ out) {
    __shared__ __align__(16) char sring[WPB * RING * SLOT];          // 42240 B
    __shared__ __align__(8)  unsigned long long smbar[WPB * RING];   // 320 B

    const int lane = threadIdx.x & 31;
    const int wib  = threadIdx.x >> 5;
    const int warp = blockIdx.x * WPB + wib;
    float acc = 0.0f;

    // Init this warp's mbarriers (arrive count 1: the producer's arrive.expect_tx).
    const unsigned int mbar0 =
        (unsigned int)__cvta_generic_to_shared(&smbar[wib * RING]);
    if (lane == 0) {
#pragma unroll
        for (int s = 0; s < RING; s++) mbar_init(mbar0 + s * 8u, 1u);
    }
    __syncthreads();
    if (lane == 0)
        asm volatile("fence.proxy.async.shared::cta;" ::: "memory");
    __syncwarp();

    {
        const int seg   = warp & (SEGS - 1);
        const int t     = warp >> 1;
        const int strip = t & (STRIPS - 1);
        const int img   = t >> 4;                        // STRIPS==16

        const float* base = labels + (size_t)img * (W * H);
        const int r0 = strip * STRIP;
        const bool rightEdge = (seg == SEGS - 1);
        const bool lastStrip = (r0 + STRIP == H);
        const int jmax = lastStrip ? (STRIP) : (STRIP + 1);  // last consumed j

        // Copy source: seg0 -> row cols [0,260); seg1 -> row cols [252,512).
        const int srcColOff = seg ? 252 : 0;
        // Per-thread read offsets inside a slot.
        const int roff  = lane * 32 + seg * 16;          // this thread's 8 floats
        const int loff  = seg ? 12 : 0;                  // lane0 left-halo byte off
        const int hoff  = 1024;                          // lane31 right halo (seg0)

        char* ringp = sring + wib * (RING * SLOT);
        const unsigned int ring0 = (unsigned int)__cvta_generic_to_shared(ringp);

        int fstage = 0;                                  // producer stage cursor
        int cstage = 0, cphase = 0;                      // consumer cursor

        // Issue bulk fetch of logical row j (row index r0-1+j, clamped at top).
        auto fetch = [&](int j) {
            if (j <= jmax) {
                if (lane == 0) {
                    int rr = r0 - 1 + j;
                    rr = (rr > 0) ? rr : 0;
                    const float* src = base + (size_t)rr * W + srcColOff;
                    bulk_fetch(ring0 + (unsigned int)fstage * SLOT, src,
                               mbar0 + (unsigned int)fstage * 8u);
                }
                fstage++; if (fstage == RING) fstage = 0;
            }
        };

        // Consume logical row j (must be called with j in order).
        auto consume = [&](int j, float x[CPT], float& xL, float& xR) {
            fetch(j + DEPTH);
            mbar_wait(mbar0 + (unsigned int)cstage * 8u, (unsigned int)cphase);
            const char* p = ringp + cstage * SLOT;
            float4 a = *reinterpret_cast<const float4*>(p + roff);
            float4 b = *reinterpret_cast<const float4*>(p + roff + 16);
            x[0]=a.x; x[1]=a.y; x[2]=a.z; x[3]=a.w;
            x[4]=b.x; x[5]=b.y; x[6]=b.z; x[7]=b.w;
            xL = (lane == 0)                ? *reinterpret_cast<const float*>(p + loff) : 0.0f;
            xR = (lane == 31 && !rightEdge) ? *reinterpret_cast<const float*>(p + hoff) : 0.0f;
            cstage++; if (cstage == RING) { cstage = 0; cphase ^= 1; }
        };

        // Prime the pipeline.
        fetch(0); fetch(1); fetch(2);

        Carry C;
        // Prologue: rows j=0 (r0-1 clamped) and j=1 (r0) -> erp = er[r0], xp = x[r0]
        {
            float xa[CPT], xb[CPT], xLa, xRa, xLb, xRb;
            consume(0, xa, xLa, xRa);
            consume(1, xb, xLb, xRb);

            float vm[CPT];
#pragma unroll
            for (int i = 0; i < CPT; i++) vm[i] = fminf(xa[i], xb[i]);
            float vmL = fminf(xLa, xLb);
            float vmR = fminf(xRa, xRb);

            float left = __shfl_up_sync(FULLM, vm[CPT-1], 1);
            if (lane == 0) left = vmL;
            C.erp[0] = fminf(left, vm[0]);
#pragma unroll
            for (int i = 1; i < CPT; i++) C.erp[i] = fminf(vm[i-1], vm[i]);
            C.erpR = fminf(vm[CPT-1], vmR);
#pragma unroll
            for (int i = 0; i < CPT; i++) C.xp[i] = xb[i];
            C.xLp = xLb; C.xRp = xRb;
        }

        if (!lastStrip) {
            for (int k = 0; k < STRIP; k++) {            // consume j = 2 .. 33
                float xc[CPT], xLc, xRc;
                consume(2 + k, xc, xLc, xRc);
                step_compute(xc, xLc, xRc, lane, rightEdge, C, acc);
            }
        } else {
            for (int k = 0; k < STRIP - 1; k++) {        // consume j = 2 .. 32
                float xc[CPT], xLc, xRc;
                consume(2 + k, xc, xLc, xRc);
                step_compute(xc, xLc, xRc, lane, rightEdge, C, acc);
            }
            final_emit(lane, rightEdge, C, acc);
        }
    }

    // Deterministic block reduction
#pragma unroll
    for (int off = 16; off; off >>= 1)
        acc += __shfl_xor_sync(FULLM, acc, off);

    __shared__ float s[WPB];
    __shared__ bool is_last;
    if (lane == 0) s[wib] = acc;
    __syncthreads();
    if (threadIdx.x == 0) {
        float tsum = 0.0f;
#pragma unroll
        for (int i = 0; i < WPB; i++) tsum += s[i];
        g_partials[blockIdx.x] = tsum;
        __threadfence();
        unsigned v = atomicAdd(&g_count, 1u);
        is_last = (v == GRID - 1);
    }
    __syncthreads();

    // Last block: deterministic final tree reduction over 512 partials.
    if (is_last) {
        __shared__ float r[BLOCK];
        r[threadIdx.x] = g_partials[threadIdx.x] + g_partials[threadIdx.x + BLOCK];
        __syncthreads();
#pragma unroll
        for (int off = BLOCK / 2; off > 0; off >>= 1) {
            if (threadIdx.x < off) r[threadIdx.x] += r[threadIdx.x + off];
            __syncthreads();
        }
        if (threadIdx.x == 0) {
            out[0] = r[0] * (1.0f / NELEM);
            g_count = 0;    // reset for graph replay
        }
    }
}

extern "C" void kernel_launch(void* const* d_in, const int* in_sizes, int n_in,
                              void* d_out, int out_size) {
    const float* labels = (const float*)d_in[0];
    float* out = (float*)d_out;
    opening_loss_kernel<<<GRID, BLOCK>>>(labels, out);
}

// round 11
// speedup vs baseline: 1.5007x; 1.5007x over previous
#include <cuda_runtime.h>
#include <cuda_bf16.h>
#include <cstdint>

#define W 512
#define H 512
#define IMGS 128                       // 16 * 8
#define STRIP 32                       // output rows per chain
#define STRIPS (H / STRIP)             // 16
#define SEGS 2                         // column segments per row
#define SEGW 256                       // cols per warp segment
#define CPT 8                          // cols per thread
#define TASKS (IMGS * STRIPS * SEGS)   // 4096 chain-tasks
#define CHAINS 2                       // chains per warp
#define WARPS (TASKS / CHAINS)         // 2048
#define BLOCK 256
#define WPB (BLOCK / 32)               // 8
#define GRID (WARPS / WPB)             // 256
#define NELEM 33554432.0f
#define FULLM 0xffffffffu

__device__ float g_partials[GRID];
__device__ unsigned int g_count;       // zero-init; last block resets

struct Carry {
    float xp[CPT];    // x[r-1]
    float erp[CPT];   // er[r-1]
    float xLp, xRp;   // halo x (lane0/lane31)
    float erpR;       // er[r-1][c1+1] (lane31)
};

__device__ __forceinline__ void load8(const float* __restrict__ p, float x[CPT]) {
    float4 a = *reinterpret_cast<const float4*>(p);
    float4 b = *reinterpret_cast<const float4*>(p + 4);
    x[0]=a.x; x[1]=a.y; x[2]=a.z; x[3]=a.w;
    x[4]=b.x; x[5]=b.y; x[6]=b.z; x[7]=b.w;
}

// Compute on row r's data (xc), emit loss for row r-1, advance carry.
__device__ __forceinline__ void step_compute(const float xc[CPT], float xLc, float xRc,
                                             int lane, bool rightEdge,
                                             Carry& C, float& acc) {
    float vm[CPT];
#pragma unroll
    for (int i = 0; i < CPT; i++) vm[i] = fminf(C.xp[i], xc[i]);  // vertical erosion
    float vmL = fminf(C.xLp, xLc);
    float vmR = fminf(C.xRp, xRc);

    // horizontal erosion: er[c] = min(vm[c-1], vm[c])
    float left = __shfl_up_sync(FULLM, vm[CPT-1], 1);
    if (lane == 0) left = vmL;                       // symmetric pad via column clamp
    float ern[CPT];
    ern[0] = fminf(left, vm[0]);
#pragma unroll
    for (int i = 1; i < CPT; i++) ern[i] = fminf(vm[i-1], vm[i]);
    float ernR = fminf(vm[CPT-1], vmR);

    // vertical dilation for row r-1
    float h[CPT];
#pragma unroll
    for (int i = 0; i < CPT; i++) h[i] = fmaxf(C.erp[i], ern[i]);
    float hR = fmaxf(C.erpR, ernR);

    // horizontal dilation + loss
    float hn = __shfl_down_sync(FULLM, h[0], 1);
    if (lane == 31) hn = rightEdge ? h[CPT-1] : hR;  // er[512]=er[511] at image edge
#pragma unroll
    for (int i = 0; i < CPT-1; i++) {
        float di = fmaxf(h[i], h[i+1]);
        float d = C.xp[i] - di;
        acc = fmaf(d, d, acc);
    }
    {
        float di = fmaxf(h[CPT-1], hn);
        float d = C.xp[CPT-1] - di;
        acc = fmaf(d, d, acc);
    }

#pragma unroll
    for (int i = 0; i < CPT; i++) { C.xp[i] = xc[i]; C.erp[i] = ern[i]; }
    C.xLp = xLc; C.xRp = xRc; C.erpR = ernR;
}

__device__ __forceinline__ void final_emit(int lane, bool rightEdge, Carry& C, float& acc) {
    float hn = __shfl_down_sync(FULLM, C.erp[0], 1);
    if (lane == 31) hn = rightEdge ? C.erp[CPT-1] : C.erpR;
#pragma unroll
    for (int i = 0; i < CPT-1; i++) {
        float di = fmaxf(C.erp[i], C.erp[i+1]);
        float d = C.xp[i] - di;
        acc = fmaf(d, d, acc);
    }
    float di = fmaxf(C.erp[CPT-1], hn);
    float d = C.xp[CPT-1] - di;
    acc = fmaf(d, d, acc);
}

// Build carry for row r0 from rows r0-1 (clamped) and r0.
__device__ __forceinline__ void init_carry(const float* __restrict__ base, int r0,
                                           int tcol, int lane, int cL, int cR,
                                           bool rightEdge, Carry& C) {
    const int rm1 = (r0 > 0) ? r0 - 1 : 0;           // x[-1]=x[0] pad
    const float* rowA = base + (size_t)rm1 * W;
    const float* rowB = base + (size_t)r0  * W;
    float xa[CPT], xb[CPT];
    load8(rowA + tcol, xa);
    load8(rowB + tcol, xb);
    float xLa = (lane == 0) ? __ldg(rowA + cL) : 0.0f;
    float xLb = (lane == 0) ? __ldg(rowB + cL) : 0.0f;
    float xRa = (!rightEdge && lane == 31) ? __ldg(rowA + cR) : 0.0f;
    float xRb = (!rightEdge && lane == 31) ? __ldg(rowB + cR) : 0.0f;

    float vm[CPT];
#pragma unroll
    for (int i = 0; i < CPT; i++) vm[i] = fminf(xa[i], xb[i]);
    float vmL = fminf(xLa, xLb);
    float vmR = fminf(xRa, xRb);

    float left = __shfl_up_sync(FULLM, vm[CPT-1], 1);
    if (lane == 0) left = vmL;
    C.erp[0] = fminf(left, vm[0]);
#pragma unroll
    for (int i = 1; i < CPT; i++) C.erp[i] = fminf(vm[i-1], vm[i]);
    C.erpR = fminf(vm[CPT-1], vmR);
#pragma unroll
    for (int i = 0; i < CPT; i++) C.xp[i] = xb[i];
    C.xLp = xLb; C.xRp = xRb;
}

__global__ void __launch_bounds__(BLOCK, 3)
opening_loss_kernel(const float* __restrict__ labels, float* __restrict__ out) {
    const int lane = threadIdx.x & 31;
    const int warp = blockIdx.x * WPB + (threadIdx.x >> 5);
    float accA = 0.0f, accB = 0.0f;

    {
        // Chain A = task `warp`, chain B = task `warp + 2048`.
        // Same seg/strip geometry; images differ by 64.
        const int seg   = warp & (SEGS - 1);
        const int t     = warp >> 1;
        const int strip = t & (STRIPS - 1);
        const int imgA  = t >> 4;                        // in [0, 64)
        const int imgB  = imgA + (IMGS / 2);             // in [64, 128)

        const float* baseA = labels + (size_t)imgA * (W * H);
        const float* baseB = labels + (size_t)imgB * (W * H);
        const int r0 = strip * STRIP;
        const int c0 = seg * SEGW;
        const bool rightEdge = (seg == SEGS - 1);
        const int cL = (c0 == 0) ? 0 : c0 - 1;           // clamp == symmetric pad
        const int cR = rightEdge ? (W - 1) : c0 + SEGW;
        const int tcol = c0 + lane * CPT;
        const bool lastStrip = (r0 + STRIP == H);

        Carry CA, CB;
        init_carry(baseA, r0, tcol, lane, cL, cR, rightEdge, CA);
        init_carry(baseB, r0, tcol, lane, cL, cR, rightEdge, CB);

        const int iters = lastStrip ? (STRIP - 1) : STRIP;   // rows r0+1 .. r0+iters
        const float* rowA = baseA + (size_t)(r0 + 1) * W;
        const float* rowB = baseB + (size_t)(r0 + 1) * W;
#pragma unroll 2
        for (int k = 0; k < iters; k++) {
            // Issue both chains' loads up front (2 KB outstanding per warp).
            float xcA[CPT], xcB[CPT];
            load8(rowA + tcol, xcA);
            load8(rowB + tcol, xcB);
            float xLa = (lane == 0)                ? __ldg(rowA + cL) : 0.0f;
            float xLb = (lane == 0)                ? __ldg(rowB + cL) : 0.0f;
            float xRa = (!rightEdge && lane == 31) ? __ldg(rowA + cR) : 0.0f;
            float xRb = (!rightEdge && lane == 31) ? __ldg(rowB + cR) : 0.0f;

            step_compute(xcA, xLa, xRa, lane, rightEdge, CA, accA);
            step_compute(xcB, xLb, xRb, lane, rightEdge, CB, accB);
            rowA += W; rowB += W;
        }
        if (lastStrip) {
            final_emit(lane, rightEdge, CA, accA);
            final_emit(lane, rightEdge, CB, accB);
        }
    }

    float acc = accA + accB;

    // Deterministic block reduction
#pragma unroll
    for (int off = 16; off; off >>= 1)
        acc += __shfl_xor_sync(FULLM, acc, off);

    __shared__ float s[WPB];
    __shared__ bool is_last;
    if (lane == 0) s[threadIdx.x >> 5] = acc;
    __syncthreads();
    if (threadIdx.x == 0) {
        float tsum = 0.0f;
#pragma unroll
        for (int i = 0; i < WPB; i++) tsum += s[i];
        g_partials[blockIdx.x] = tsum;
        __threadfence();
        unsigned v = atomicAdd(&g_count, 1u);
        is_last = (v == GRID - 1);
    }
    __syncthreads();

    // Last block: deterministic final tree reduction over 256 partials.
    if (is_last) {
        __shared__ float r[BLOCK];
        r[threadIdx.x] = g_partials[threadIdx.x];
        __syncthreads();
#pragma unroll
        for (int off = BLOCK / 2; off > 0; off >>= 1) {
            if (threadIdx.x < off) r[threadIdx.x] += r[threadIdx.x + off];
            __syncthreads();
        }
        if (threadIdx.x == 0) {
            out[0] = r[0] * (1.0f / NELEM);
            g_count = 0;    // reset for graph replay
        }
    }
}

extern "C" void kernel_launch(void* const* d_in, const int* in_sizes, int n_in,
                              void* d_out, int out_size) {
    const float* labels = (const float*)d_in[0];
    float* out = (float*)d_out;
    opening_loss_kernel<<<GRID, BLOCK>>>(labels, out);
}

// round 12
// speedup vs baseline: 1.6949x; 1.1294x over previous
#include <cuda_runtime.h>
#include <cuda_bf16.h>
#include <cstdint>

#define W 512
#define H 512
#define IMGS 128                       // 16 * 8
#define STRIP 32                       // output rows per warp-task
#define STRIPS (H / STRIP)             // 16
#define SEGS 2                         // column segments per row
#define SEGW 256                       // cols per warp segment
#define CPT 8                          // cols per thread
#define TASKS (IMGS * STRIPS * SEGS)   // 4096 warp-tasks
#define BLOCK 256
#define WPB (BLOCK / 32)               // 8
#define GRID (TASKS / WPB)             // 512
#define NELEM 33554432.0f
#define FULLM 0xffffffffu

__device__ float g_partials[GRID];
__device__ unsigned int g_count;       // zero-init; last block resets

struct Carry {
    float xp[CPT];    // x[r-1]
    float erp[CPT];   // er[r-1]
    float xLp, xRp;   // halo x (lane0/lane31)
    float erpR;       // er[r-1][c1+1] (lane31)
};

__device__ __forceinline__ void load8(const float* __restrict__ p, float x[CPT]) {
    float4 a = *reinterpret_cast<const float4*>(p);
    float4 b = *reinterpret_cast<const float4*>(p + 4);
    x[0]=a.x; x[1]=a.y; x[2]=a.z; x[3]=a.w;
    x[4]=b.x; x[5]=b.y; x[6]=b.z; x[7]=b.w;
}

// Load one row's worth (8 floats + 2 predicated halo scalars).
__device__ __forceinline__ void loadrow(const float* __restrict__ row, int tcol,
                                        int lane, int cL, int cR, bool rightEdge,
                                        float x[CPT], float& xL, float& xR) {
    load8(row + tcol, x);
    xL = (lane == 0)                ? __ldg(row + cL) : 0.0f;
    xR = (!rightEdge && lane == 31) ? __ldg(row + cR) : 0.0f;
}

// Compute on row r's data (xc), emit loss for row r-1, advance carry.
__device__ __forceinline__ void step_compute(const float xc[CPT], float xLc, float xRc,
                                             int lane, bool rightEdge,
                                             Carry& C, float& acc) {
    float vm[CPT];
#pragma unroll
    for (int i = 0; i < CPT; i++) vm[i] = fminf(C.xp[i], xc[i]);  // vertical erosion
    float vmL = fminf(C.xLp, xLc);
    float vmR = fminf(C.xRp, xRc);

    // horizontal erosion: er[c] = min(vm[c-1], vm[c])
    float left = __shfl_up_sync(FULLM, vm[CPT-1], 1);
    if (lane == 0) left = vmL;                       // symmetric pad via column clamp
    float ern[CPT];
    ern[0] = fminf(left, vm[0]);
#pragma unroll
    for (int i = 1; i < CPT; i++) ern[i] = fminf(vm[i-1], vm[i]);
    float ernR = fminf(vm[CPT-1], vmR);

    // vertical dilation for row r-1
    float h[CPT];
#pragma unroll
    for (int i = 0; i < CPT; i++) h[i] = fmaxf(C.erp[i], ern[i]);
    float hR = fmaxf(C.erpR, ernR);

    // horizontal dilation + loss
    float hn = __shfl_down_sync(FULLM, h[0], 1);
    if (lane == 31) hn = rightEdge ? h[CPT-1] : hR;  // er[512]=er[511] at image edge
#pragma unroll
    for (int i = 0; i < CPT-1; i++) {
        float di = fmaxf(h[i], h[i+1]);
        float d = C.xp[i] - di;
        acc = fmaf(d, d, acc);
    }
    {
        float di = fmaxf(h[CPT-1], hn);
        float d = C.xp[CPT-1] - di;
        acc = fmaf(d, d, acc);
    }

#pragma unroll
    for (int i = 0; i < CPT; i++) { C.xp[i] = xc[i]; C.erp[i] = ern[i]; }
    C.xLp = xLc; C.xRp = xRc; C.erpR = ernR;
}

__device__ __forceinline__ void final_emit(int lane, bool rightEdge, Carry& C, float& acc) {
    float hn = __shfl_down_sync(FULLM, C.erp[0], 1);
    if (lane == 31) hn = rightEdge ? C.erp[CPT-1] : C.erpR;
#pragma unroll
    for (int i = 0; i < CPT-1; i++) {
        float di = fmaxf(C.erp[i], C.erp[i+1]);
        float d = C.xp[i] - di;
        acc = fmaf(d, d, acc);
    }
    float di = fmaxf(C.erp[CPT-1], hn);
    float d = C.xp[CPT-1] - di;
    acc = fmaf(d, d, acc);
}

__global__ void __launch_bounds__(BLOCK, 3)
opening_loss_kernel(const float* __restrict__ labels, float* __restrict__ out) {
    const int lane = threadIdx.x & 31;
    const int warp = blockIdx.x * WPB + (threadIdx.x >> 5);
    float acc = 0.0f;

    {
        const int seg   = warp & (SEGS - 1);
        const int t     = warp >> 1;
        const int strip = t & (STRIPS - 1);
        const int img   = t >> 4;                        // STRIPS==16

        const float* base = labels + (size_t)img * (W * H);
        const int r0 = strip * STRIP;
        const int c0 = seg * SEGW;
        const bool rightEdge = (seg == SEGS - 1);
        const int cL = (c0 == 0) ? 0 : c0 - 1;           // clamp == symmetric pad
        const int cR = rightEdge ? (W - 1) : c0 + SEGW;
        const int tcol = c0 + lane * CPT;
        const bool lastStrip = (r0 + STRIP == H);

        Carry C;
        // Prologue: erp = er[r0], xp = x[r0]
        {
            const int rm1 = (r0 > 0) ? r0 - 1 : 0;       // x[-1]=x[0] pad
            const float* rowA = base + (size_t)rm1 * W;
            const float* rowB = base + (size_t)r0  * W;
            float xa[CPT], xb[CPT], xLa, xRa, xLb, xRb;
            loadrow(rowA, tcol, lane, cL, cR, rightEdge, xa, xLa, xRa);
            loadrow(rowB, tcol, lane, cL, cR, rightEdge, xb, xLb, xRb);

            float vm[CPT];
#pragma unroll
            for (int i = 0; i < CPT; i++) vm[i] = fminf(xa[i], xb[i]);
            float vmL = fminf(xLa, xLb);
            float vmR = fminf(xRa, xRb);

            float left = __shfl_up_sync(FULLM, vm[CPT-1], 1);
            if (lane == 0) left = vmL;
            C.erp[0] = fminf(left, vm[0]);
#pragma unroll
            for (int i = 1; i < CPT; i++) C.erp[i] = fminf(vm[i-1], vm[i]);
            C.erpR = fminf(vm[CPT-1], vmR);
#pragma unroll
            for (int i = 0; i < CPT; i++) C.xp[i] = xb[i];
            C.xLp = xLb; C.xRp = xRb;
        }

        if (!lastStrip) {
            // Parity-pipelined mainloop: buffers A/B alternate; the next row's
            // loads are always issued before the current row's compute.
            const float* row = base + (size_t)(r0 + 1) * W;
            float xA[CPT], xB[CPT], xLA, xRA, xLB, xRB;
            loadrow(row, tcol, lane, cL, cR, rightEdge, xA, xLA, xRA);   // r0+1
#pragma unroll 1
            for (int k = 0; k < STRIP - 2; k += 2) {
                loadrow(row + W, tcol, lane, cL, cR, rightEdge, xB, xLB, xRB);
                step_compute(xA, xLA, xRA, lane, rightEdge, C, acc);
                loadrow(row + 2 * W, tcol, lane, cL, cR, rightEdge, xA, xLA, xRA);
                step_compute(xB, xLB, xRB, lane, rightEdge, C, acc);
                row += 2 * W;
            }
            // Last pair (rows r0+STRIP-1, r0+STRIP): no further prefetch.
            loadrow(row + W, tcol, lane, cL, cR, rightEdge, xB, xLB, xRB);
            step_compute(xA, xLA, xRA, lane, rightEdge, C, acc);
            step_compute(xB, xLB, xRB, lane, rightEdge, C, acc);
        } else {
            // Bottom strip (1/16 of tasks): simple serial loop + final emit.
            const float* row = base + (size_t)(r0 + 1) * W;
            for (int r = r0 + 1; r < H; r++) {
                float xc[CPT], xLc, xRc;
                loadrow(row, tcol, lane, cL, cR, rightEdge, xc, xLc, xRc);
                step_compute(xc, xLc, xRc, lane, rightEdge, C, acc);
                row += W;
            }
            final_emit(lane, rightEdge, C, acc);
        }
    }

    // Deterministic block reduction
#pragma unroll
    for (int off = 16; off; off >>= 1)
        acc += __shfl_xor_sync(FULLM, acc, off);

    __shared__ float s[WPB];
    __shared__ bool is_last;
    if (lane == 0) s[threadIdx.x >> 5] = acc;
    __syncthreads();
    if (threadIdx.x == 0) {
        float tsum = 0.0f;
#pragma unroll
        for (int i = 0; i < WPB; i++) tsum += s[i];
        g_partials[blockIdx.x] = tsum;
        __threadfence();
        unsigned v = atomicAdd(&g_count, 1u);
        is_last = (v == GRID - 1);
    }
    __syncthreads();

    // Last block: deterministic final tree reduction over 512 partials.
    if (is_last) {
        __shared__ float r[BLOCK];
        r[threadIdx.x] = g_partials[threadIdx.x] + g_partials[threadIdx.x + BLOCK];
        __syncthreads();
#pragma unroll
        for (int off = BLOCK / 2; off > 0; off >>= 1) {
            if (threadIdx.x < off) r[threadIdx.x] += r[threadIdx.x + off];
            __syncthreads();
        }
        if (threadIdx.x == 0) {
            out[0] = r[0] * (1.0f / NELEM);
            g_count = 0;    // reset for graph replay
        }
    }
}

extern "C" void kernel_launch(void* const* d_in, const int* in_sizes, int n_in,
                              void* d_out, int out_size) {
    const float* labels = (const float*)d_in[0];
    float* out = (float*)d_out;
    opening_loss_kernel<<<GRID, BLOCK>>>(labels, out);
}

// round 13
// speedup vs baseline: 2.3050x; 1.3600x over previous
#include <cuda_runtime.h>
#include <cuda_bf16.h>
#include <cstdint>

#define W 512
#define H 512
#define IMGS 128                       // 16 * 8
#define STRIP 32                       // output rows per warp-task
#define STRIPS (H / STRIP)             // 16
#define SEGS 2                         // column segments per row
#define SEGW 256                       // cols per warp segment
#define CPT 8                          // cols per thread
#define TASKS (IMGS * STRIPS * SEGS)   // 4096 warp-tasks
#define BLOCK 128
#define WPB (BLOCK / 32)               // 4
#define GRID (TASKS / WPB)             // 1024 blocks, all resident in one wave
#define NELEM 33554432.0f
#define FULLM 0xffffffffu

__device__ float g_partials[GRID];
__device__ unsigned int g_count;       // zero-init; last block resets

struct Carry {
    float xp[CPT];    // x[r-1] at this thread's cols
    float erp[CPT];   // er[r-1]
    float xLp, xRp;   // halo cols of x[r-1] (lane0 / lane31 only)
    float erpR;       // er[r-1][c1+1]     (lane31 only)
};

__device__ __forceinline__ void load8(const float* __restrict__ p, float x[CPT]) {
    float4 a = *reinterpret_cast<const float4*>(p);
    float4 b = *reinterpret_cast<const float4*>(p + 4);
    x[0]=a.x; x[1]=a.y; x[2]=a.z; x[3]=a.w;
    x[4]=b.x; x[5]=b.y; x[6]=b.z; x[7]=b.w;
}

// Consume row r, emit loss for row r-1.
__device__ __forceinline__ void step_row(const float* __restrict__ tp,
                                         const float* __restrict__ row,
                                         int lane, int cL, int cR, bool rightEdge,
                                         Carry& C, float& acc) {
    float xc[CPT];
    load8(tp, xc);
    float xLc = (lane == 0)                ? __ldg(row + cL) : 0.0f;
    float xRc = (!rightEdge && lane == 31) ? __ldg(row + cR) : 0.0f;

    float vm[CPT];
#pragma unroll
    for (int i = 0; i < CPT; i++) vm[i] = fminf(C.xp[i], xc[i]);  // vertical erosion
    float vmL = fminf(C.xLp, xLc);
    float vmR = fminf(C.xRp, xRc);

    // horizontal erosion: er[c] = min(vm[c-1], vm[c])
    float left = __shfl_up_sync(FULLM, vm[CPT-1], 1);
    if (lane == 0) left = vmL;                       // symmetric pad via cL clamp
    float ern[CPT];
    ern[0] = fminf(left, vm[0]);
#pragma unroll
    for (int i = 1; i < CPT; i++) ern[i] = fminf(vm[i-1], vm[i]);
    float ernR = fminf(vm[CPT-1], vmR);

    // vertical dilation for row r-1: h = max(er[r-1], er[r])
    float h[CPT];
#pragma unroll
    for (int i = 0; i < CPT; i++) h[i] = fmaxf(C.erp[i], ern[i]);
    float hR = fmaxf(C.erpR, ernR);

    // horizontal dilation + loss: di[c] = max(h[c], h[c+1])
    float hn = __shfl_down_sync(FULLM, h[0], 1);
    if (lane == 31) hn = rightEdge ? h[CPT-1] : hR;  // er[512]=er[511] at image edge
#pragma unroll
    for (int i = 0; i < CPT-1; i++) {
        float di = fmaxf(h[i], h[i+1]);
        float d = C.xp[i] - di;
        acc = fmaf(d, d, acc);
    }
    {
        float di = fmaxf(h[CPT-1], hn);
        float d = C.xp[CPT-1] - di;
        acc = fmaf(d, d, acc);
    }

#pragma unroll
    for (int i = 0; i < CPT; i++) { C.xp[i] = xc[i]; C.erp[i] = ern[i]; }
    C.xLp = xLc; C.xRp = xRc; C.erpR = ernR;
}

// Emit bottom image row (r = H-1): er[H] := er[H-1], so h == erp.
__device__ __forceinline__ void final_emit(int lane, bool rightEdge, Carry& C, float& acc) {
    float hn = __shfl_down_sync(FULLM, C.erp[0], 1);
    if (lane == 31) hn = rightEdge ? C.erp[CPT-1] : C.erpR;
#pragma unroll
    for (int i = 0; i < CPT-1; i++) {
        float di = fmaxf(C.erp[i], C.erp[i+1]);
        float d = C.xp[i] - di;
        acc = fmaf(d, d, acc);
    }
    float di = fmaxf(C.erp[CPT-1], hn);
    float d = C.xp[CPT-1] - di;
    acc = fmaf(d, d, acc);
}

__global__ void __launch_bounds__(BLOCK, 8)
opening_loss_kernel(const float* __restrict__ labels, float* __restrict__ out) {
    const int lane = threadIdx.x & 31;
    const int warp = blockIdx.x * WPB + (threadIdx.x >> 5);
    const int seg   = warp & (SEGS - 1);
    const int t     = warp >> 1;
    const int strip = t & (STRIPS - 1);
    const int img   = t >> 4;                        // STRIPS==16

    const float* base = labels + (size_t)img * (W * H);
    const int r0 = strip * STRIP;
    const int c0 = seg * SEGW;
    const bool rightEdge = (seg == SEGS - 1);
    const int cL = (c0 == 0) ? 0 : c0 - 1;           // clamp == symmetric pad
    const int cR = rightEdge ? (W - 1) : c0 + SEGW;  // never loaded when rightEdge
    const int tcol = c0 + lane * CPT;
    const bool lastStrip = (r0 + STRIP == H);

    Carry C;
    float acc = 0.0f;

    // Prologue: erp = er[r0], xp = x[r0]
    {
        const int rm1 = (r0 > 0) ? r0 - 1 : 0;       // x[-1]=x[0] pad
        const float* rowA = base + (size_t)rm1 * W;
        const float* rowB = base + (size_t)r0  * W;
        float xa[CPT], xb[CPT];
        load8(rowA + tcol, xa);
        load8(rowB + tcol, xb);
        float xLa = (lane == 0) ? __ldg(rowA + cL) : 0.0f;
        float xLb = (lane == 0) ? __ldg(rowB + cL) : 0.0f;
        float xRa = (!rightEdge && lane == 31) ? __ldg(rowA + cR) : 0.0f;
        float xRb = (!rightEdge && lane == 31) ? __ldg(rowB + cR) : 0.0f;

        float vm[CPT];
#pragma unroll
        for (int i = 0; i < CPT; i++) vm[i] = fminf(xa[i], xb[i]);
        float vmL = fminf(xLa, xLb);
        float vmR = fminf(xRa, xRb);

        float left = __shfl_up_sync(FULLM, vm[CPT-1], 1);
        if (lane == 0) left = vmL;
        C.erp[0] = fminf(left, vm[0]);
#pragma unroll
        for (int i = 1; i < CPT; i++) C.erp[i] = fminf(vm[i-1], vm[i]);
        C.erpR = fminf(vm[CPT-1], vmR);
#pragma unroll
        for (int i = 0; i < CPT; i++) C.xp[i] = xb[i];
        C.xLp = xLb; C.xRp = xRb;
    }

    if (!lastStrip) {
        const float* row = base + (size_t)(r0 + 1) * W;
#pragma unroll 4
        for (int k = 0; k < STRIP; k++) {
            step_row(row + tcol, row, lane, cL, cR, rightEdge, C, acc);
            row += W;
        }
    } else {
        const float* row = base + (size_t)(r0 + 1) * W;
        for (int r = r0 + 1; r < H; r++) {
            step_row(row + tcol, row, lane, cL, cR, rightEdge, C, acc);
            row += W;
        }
        final_emit(lane, rightEdge, C, acc);
    }

    // Deterministic block reduction
#pragma unroll
    for (int off = 16; off; off >>= 1)
        acc += __shfl_xor_sync(FULLM, acc, off);

    __shared__ float s[WPB];
    __shared__ bool is_last;
    if (lane == 0) s[threadIdx.x >> 5] = acc;
    __syncthreads();
    if (threadIdx.x == 0) {
        float tsum = 0.0f;
#pragma unroll
        for (int i = 0; i < WPB; i++) tsum += s[i];
        g_partials[blockIdx.x] = tsum;
        __threadfence();
        unsigned v = atomicAdd(&g_count, 1u);
        is_last = (v == GRID - 1);
    }
    __syncthreads();

    // Last block: deterministic final tree reduction over 1024 partials.
    if (is_last) {
        __shared__ float r[BLOCK];
        float v = 0.0f;
#pragma unroll
        for (int k = 0; k < GRID / BLOCK; k++)           // 8 strided partials each
            v += g_partials[threadIdx.x + k * BLOCK];
        r[threadIdx.x] = v;
        __syncthreads();
#pragma unroll
        for (int off = BLOCK / 2; off > 0; off >>= 1) {
            if (threadIdx.x < off) r[threadIdx.x] += r[threadIdx.x + off];
            __syncthreads();
        }
        if (threadIdx.x == 0) {
            out[0] = r[0] * (1.0f / NELEM);
            g_count = 0;    // reset for graph replay
        }
    }
}

extern "C" void kernel_launch(void* const* d_in, const int* in_sizes, int n_in,
                              void* d_out, int out_size) {
    const float* labels = (const float*)d_in[0];
    float* out = (float*)d_out;
    opening_loss_kernel<<<GRID, BLOCK>>>(labels, out);
}

// round 14
// speedup vs baseline: 2.7214x; 1.1806x over previous
#include <cuda_runtime.h>
#include <cuda_bf16.h>
#include <cstdint>

#define W 512
#define H 512
#define IMGS 128                       // 16 * 8
#define STRIPB 64                      // rows per CTA
#define STRIPS (H / STRIPB)            // 8
#define BLOCK 128
#define WPB 4
#define GRID (IMGS * STRIPS)           // 1024 CTAs, one wave at 7/SM
#define CPT 8
#define NELEM 33554432.0f
#define FULLM 0xffffffffu

#define CHROWS 3                       // rows per bulk chunk
#define CHB (CHROWS * W * 4)           // 6144 bytes
#define RINGN 2                        // stages per pipe
#define PIPEB (RINGN * CHB)            // 12288 bytes

__device__ float g_partials[GRID];
__device__ unsigned int g_count;       // zero-init; last block resets

__device__ __forceinline__ void mbar_init(unsigned bar, unsigned cnt) {
    asm volatile("mbarrier.init.shared.b64 [%0], %1;" :: "r"(bar), "r"(cnt) : "memory");
}
__device__ __forceinline__ void mbar_wait(unsigned bar, unsigned parity) {
    asm volatile(
        "{\n\t.reg .pred P;\n\t"
        "WL_%=:\n\t"
        "mbarrier.try_wait.parity.acquire.cta.shared::cta.b64 P, [%0], %1, 0x989680;\n\t"
        "@P bra.uni WD_%=;\n\t"
        "bra.uni WL_%=;\n\t"
        "WD_%=:\n\t}"
        :: "r"(bar), "r"(parity) : "memory");
}
__device__ __forceinline__ void mbar_arrive(unsigned bar) {
    asm volatile("mbarrier.arrive.shared.b64 _, [%0];" :: "r"(bar) : "memory");
}
__device__ __forceinline__ void mbar_expect(unsigned bar, unsigned bytes) {
    asm volatile("mbarrier.arrive.expect_tx.shared.b64 _, [%0], %1;"
                 :: "r"(bar), "r"(bytes) : "memory");
}
__device__ __forceinline__ void bulk_cp(unsigned dst, const float* src, unsigned bytes,
                                        unsigned bar) {
    asm volatile("cp.async.bulk.shared::cta.global.mbarrier::complete_tx::bytes "
                 "[%0], [%1], %2, [%3];"
                 :: "r"(dst), "l"(src), "r"(bytes), "r"(bar) : "memory");
}

struct Carry {
    float xp[CPT];    // x[r-1]
    float erp[CPT];   // er[r-1]
    float xLp, xRp;   // halo x (lane0/lane31)
    float erpR;       // er[r-1][c1+1] (lane31)
};

// R3's proven compute step: consume row r data, emit loss for row r-1.
__device__ __forceinline__ void step_compute(const float xc[CPT], float xLc, float xRc,
                                             int lane, bool rightEdge,
                                             Carry& C, float& acc) {
    float vm[CPT];
#pragma unroll
    for (int i = 0; i < CPT; i++) vm[i] = fminf(C.xp[i], xc[i]);  // vertical erosion
    float vmL = fminf(C.xLp, xLc);
    float vmR = fminf(C.xRp, xRc);

    float left = __shfl_up_sync(FULLM, vm[CPT-1], 1);
    if (lane == 0) left = vmL;                       // symmetric pad via column clamp
    float ern[CPT];
    ern[0] = fminf(left, vm[0]);
#pragma unroll
    for (int i = 1; i < CPT; i++) ern[i] = fminf(vm[i-1], vm[i]);
    float ernR = fminf(vm[CPT-1], vmR);

    float h[CPT];
#pragma unroll
    for (int i = 0; i < CPT; i++) h[i] = fmaxf(C.erp[i], ern[i]);
    float hR = fmaxf(C.erpR, ernR);

    float hn = __shfl_down_sync(FULLM, h[0], 1);
    if (lane == 31) hn = rightEdge ? h[CPT-1] : hR;  // er[512]=er[511] at image edge
#pragma unroll
    for (int i = 0; i < CPT-1; i++) {
        float di = fmaxf(h[i], h[i+1]);
        float d = C.xp[i] - di;
        acc = fmaf(d, d, acc);
    }
    {
        float di = fmaxf(h[CPT-1], hn);
        float d = C.xp[CPT-1] - di;
        acc = fmaf(d, d, acc);
    }

#pragma unroll
    for (int i = 0; i < CPT; i++) { C.xp[i] = xc[i]; C.erp[i] = ern[i]; }
    C.xLp = xLc; C.xRp = xRc; C.erpR = ernR;
}

__device__ __forceinline__ void final_emit(int lane, bool rightEdge, Carry& C, float& acc) {
    float hn = __shfl_down_sync(FULLM, C.erp[0], 1);
    if (lane == 31) hn = rightEdge ? C.erp[CPT-1] : C.erpR;
#pragma unroll
    for (int i = 0; i < CPT-1; i++) {
        float di = fmaxf(C.erp[i], C.erp[i+1]);
        float d = C.xp[i] - di;
        acc = fmaf(d, d, acc);
    }
    float di = fmaxf(C.erp[CPT-1], hn);
    float d = C.xp[CPT-1] - di;
    acc = fmaf(d, d, acc);
}

__global__ void __launch_bounds__(BLOCK, 7)
opening_loss_kernel(const float* __restrict__ labels, float* __restrict__ out) {
    __shared__ __align__(16) char sdata[2 * PIPEB];            // 24576 B
    __shared__ __align__(8) unsigned long long mbars[8];

    const int lane = threadIdx.x & 31;
    const int wid  = threadIdx.x >> 5;
    const int pipe = wid >> 1;         // 0: rows [r0, r0+31]; 1: rows [r0+32, r0+63]
    const int cw   = wid & 1;          // column half within pipe

    const int img   = blockIdx.x >> 3;
    const int strip = blockIdx.x & (STRIPS - 1);
    const int r0 = strip * STRIPB;
    const float* base = labels + (size_t)img * (W * H);

    const unsigned mb0 = (unsigned)__cvta_generic_to_shared(mbars);
    // layout: [pipe*4+0,1]=full[stage], [pipe*4+2,3]=empty[stage]
    if (threadIdx.x == 0) {
#pragma unroll
        for (int p = 0; p < 2; p++) {
            mbar_init(mb0 + (p*4+0)*8u, 1u);
            mbar_init(mb0 + (p*4+1)*8u, 1u);
            mbar_init(mb0 + (p*4+2)*8u, 2u);
            mbar_init(mb0 + (p*4+3)*8u, 2u);
        }
    }
    __syncthreads();

    const bool p1 = (pipe == 1);
    const bool lastStrip = (r0 + STRIPB == H);
    const int rA    = p1 ? (r0 + 31) : ((r0 > 0) ? r0 - 1 : 0);   // first stream row
    const int rLast = p1 ? (lastStrip ? (H - 1) : (r0 + STRIPB)) : (r0 + 32);
    const int NC = (rLast - rA) / CHROWS + 1;                     // chunks this pipe
    const unsigned psm = (unsigned)__cvta_generic_to_shared(sdata) + pipe * PIPEB;
    const unsigned fullb  = mb0 + (unsigned)(pipe*4)   * 8u;      // + stage*8
    const unsigned emptyb = mb0 + (unsigned)(pipe*4+2) * 8u;

    // Producer (whole warp cw==0 executes; lane 0 issues).
    auto produce = [&](int n) {
        if (n < NC) {
            if (n >= RINGN)
                mbar_wait(emptyb + (unsigned)(n & 1) * 8u, (unsigned)(((n >> 1) - 1) & 1));
            if (lane == 0) {
                mbar_expect(fullb + (unsigned)(n & 1) * 8u, CHB);
                bulk_cp(psm + (unsigned)(n & 1) * CHB,
                        base + (size_t)(rA + n * CHROWS) * W, CHB,
                        fullb + (unsigned)(n & 1) * 8u);
            }
            __syncwarp();
        }
    };

    if (cw == 0) {
        if (lane == 0)
            asm volatile("fence.proxy.async.shared::cta;" ::: "memory");
        __syncwarp();
        produce(0);
        produce(1);
    }

    const int c0 = cw * 256;
    const bool rightEdge = (cw == 1);
    const int cL = (c0 == 0) ? 0 : c0 - 1;           // clamp == symmetric pad
    const int cR = c0 + 256;                          // only read when !rightEdge
    const int tcol = c0 + lane * CPT;

    int cc = 0, slot = 0;
    mbar_wait(fullb + 0u, 0u);                        // chunk 0 ready

    auto read_row = [&](float x[CPT], float& xL, float& xR) {
        const char* p = sdata + pipe * PIPEB + (cc & 1) * CHB + slot * (W * 4);
        float4 a = *reinterpret_cast<const float4*>(p + tcol * 4);
        float4 b = *reinterpret_cast<const float4*>(p + tcol * 4 + 16);
        x[0]=a.x; x[1]=a.y; x[2]=a.z; x[3]=a.w;
        x[4]=b.x; x[5]=b.y; x[6]=b.z; x[7]=b.w;
        xL = (lane == 0)                ? *reinterpret_cast<const float*>(p + cL * 4) : 0.0f;
        xR = (!rightEdge && lane == 31) ? *reinterpret_cast<const float*>(p + cR * 4) : 0.0f;
    };
    auto next_row = [&]() {
        slot++;
        if (slot == CHROWS) {
            __syncwarp();
            if (lane == 0) mbar_arrive(emptyb + (unsigned)(cc & 1) * 8u);
            cc++;
            if (cw == 0) produce(cc + 1);
            mbar_wait(fullb + (unsigned)(cc & 1) * 8u, (unsigned)((cc >> 1) & 1));
            slot = 0;
        }
    };

    Carry C;
    float acc = 0.0f;

    // Prologue: rows rA ("r-1", clamped) and start row -> C for the first output.
    {
        float xa[CPT], xb[CPT], xLa, xRa, xLb, xRb;
        read_row(xa, xLa, xRa);
        const int aP2 = p1 ? (r0 + 32) : r0;
        if (aP2 != rA) {                 // all cases except strip0/pipe0
            next_row();
            read_row(xb, xLb, xRb);
        } else {                         // top image edge: x[-1] = x[0]
#pragma unroll
            for (int i = 0; i < CPT; i++) xb[i] = xa[i];
            xLb = xLa; xRb = xRa;
        }

        float vm[CPT];
#pragma unroll
        for (int i = 0; i < CPT; i++) vm[i] = fminf(xa[i], xb[i]);
        float vmL = fminf(xLa, xLb);
        float vmR = fminf(xRa, xRb);

        float left = __shfl_up_sync(FULLM, vm[CPT-1], 1);
        if (lane == 0) left = vmL;
        C.erp[0] = fminf(left, vm[0]);
#pragma unroll
        for (int i = 1; i < CPT; i++) C.erp[i] = fminf(vm[i-1], vm[i]);
        C.erpR = fminf(vm[CPT-1], vmR);
#pragma unroll
        for (int i = 0; i < CPT; i++) C.xp[i] = xb[i];
        C.xLp = xLb; C.xRp = xRb;
    }

    // Body: outputs startOut..endBody, each consuming the next stream row.
    {
        const int startOut = p1 ? (r0 + 32) : r0;
        const int endBody  = p1 ? (lastStrip ? (H - 2) : (r0 + 63)) : (r0 + 31);
        for (int o = startOut; o <= endBody; o++) {
            float xc[CPT], xLc, xRc;
            next_row();
            read_row(xc, xLc, xRc);
            step_compute(xc, xLc, xRc, lane, rightEdge, C, acc);
        }
        if (p1 && lastStrip) final_emit(lane, rightEdge, C, acc);
    }

    // Deterministic block reduction
#pragma unroll
    for (int off = 16; off; off >>= 1)
        acc += __shfl_xor_sync(FULLM, acc, off);

    __shared__ float s[WPB];
    __shared__ bool is_last;
    if (lane == 0) s[wid] = acc;
    __syncthreads();
    if (threadIdx.x == 0) {
        float tsum = 0.0f;
#pragma unroll
        for (int i = 0; i < WPB; i++) tsum += s[i];
        g_partials[blockIdx.x] = tsum;
        __threadfence();
        unsigned v = atomicAdd(&g_count, 1u);
        is_last = (v == GRID - 1);
    }
    __syncthreads();

    // Last block: deterministic final tree reduction over 1024 partials.
    if (is_last) {
        __shared__ float r[BLOCK];
        float v = 0.0f;
#pragma unroll
        for (int k = 0; k < GRID / BLOCK; k++)
            v += g_partials[threadIdx.x + k * BLOCK];
        r[threadIdx.x] = v;
        __syncthreads();
#pragma unroll
        for (int off = BLOCK / 2; off > 0; off >>= 1) {
            if (threadIdx.x < off) r[threadIdx.x] += r[threadIdx.x + off];
            __syncthreads();
        }
        if (threadIdx.x == 0) {
            out[0] = r[0] * (1.0f / NELEM);
            g_count = 0;    // reset for graph replay
        }
    }
}

extern "C" void kernel_launch(void* const* d_in, const int* in_sizes, int n_in,
                              void* d_out, int out_size) {
    const float* labels = (const float*)d_in[0];
    float* out = (float*)d_out;
    opening_loss_kernel<<<GRID, BLOCK>>>(labels, out);
}